// round 1
// baseline (speedup 1.0000x reference)
#include <cuda_runtime.h>
#include <math.h>

#define H    128
#define NB   64
#define SQ   32
#define SD   256
#define NQTOK (NB*SQ)   // 2048
#define NDTOK (NB*SD)   // 16384

// Scratch (allocation-free rule: __device__ globals)
__device__ float g_qn[NQTOK*H];     // normalized q (unmasked)
__device__ float g_dn[NDTOK*H];     // normalized d (unmasked)
__device__ float g_scores[NB*NB];
__device__ float g_avgq[NB];
__device__ float g_avgd[NB];

// ---------------------------------------------------------------------------
// Kernel 1: token-wise L2 normalize. 1 warp per token, 4 elems/lane (float4).
// which==0 -> write g_qn, which==1 -> write g_dn
// ---------------------------------------------------------------------------
__global__ void normalize_kernel(const float* __restrict__ in, int ntok, int which)
{
    int wid  = threadIdx.x >> 5;
    int lane = threadIdx.x & 31;
    int tok  = blockIdx.x * 8 + wid;
    if (tok >= ntok) return;

    float4 v = ((const float4*)in)[tok * 32 + lane];
    float ss = v.x*v.x + v.y*v.y + v.z*v.z + v.w*v.w;
    #pragma unroll
    for (int o = 16; o; o >>= 1) ss += __shfl_xor_sync(0xffffffffu, ss, o);

    float n = sqrtf(ss);
    float scale = 1.0f / fmaxf(n, 1e-12f);   // matches x / max(||x||, eps)
    v.x *= scale; v.y *= scale; v.z *= scale; v.w *= scale;

    float* out = which ? g_dn : g_qn;
    ((float4*)out)[tok * 32 + lane] = v;
}

// ---------------------------------------------------------------------------
// Kernel 2: per-batch average off-diagonal pairwise similarity via
//   sum_{s!=t} q_s.q_t = ||sum_s q_s||^2 - sum_s ||q_s||^2
// One block per batch, 128 threads (one per h).
// ---------------------------------------------------------------------------
__global__ void avgsim_kernel()
{
    int b = blockIdx.x;
    int h = threadIdx.x;       // 0..127
    __shared__ float r1[128], r2[128];

    // ---- q part ----
    float sum = 0.f, ss = 0.f;
    #pragma unroll 4
    for (int s = 0; s < SQ; s++) {
        float v = g_qn[(b*SQ + s)*H + h];
        sum += v; ss += v*v;
    }
    r1[h] = sum * sum;  r2[h] = ss;
    __syncthreads();
    #pragma unroll
    for (int o = 64; o; o >>= 1) {
        if (h < o) { r1[h] += r1[h+o]; r2[h] += r2[h+o]; }
        __syncthreads();
    }
    if (h == 0) g_avgq[b] = (r1[0] - r2[0]) * (1.0f / (SQ * (SQ - 1)));
    __syncthreads();

    // ---- d part ----
    sum = 0.f; ss = 0.f;
    #pragma unroll 4
    for (int s = 0; s < SD; s++) {
        float v = g_dn[(b*SD + s)*H + h];
        sum += v; ss += v*v;
    }
    r1[h] = sum * sum;  r2[h] = ss;
    __syncthreads();
    #pragma unroll
    for (int o = 64; o; o >>= 1) {
        if (h < o) { r1[h] += r1[h+o]; r2[h] += r2[h+o]; }
        __syncthreads();
    }
    if (h == 0) g_avgd[b] = (r1[0] - r2[0]) * (1.0f / ((float)SD * (SD - 1)));
}

// ---------------------------------------------------------------------------
// Kernel 3: max-GEMM. scores[a][b] = max_{s,t} (q[a,s].d[b,t]) * qm * dm
// Treated as flat GEMM Q[2048,128] x D^T with masked rows zeroed at load, and
// a max-reduction epilogue per (a,b) 32x256 panel.
//
// Block: (bb = doc batch b, by = row panel of 128 flat q rows = 4 a's).
// Tiles: BMxBN = 128x128 output (looped twice over nt for Sd=256),
//        BK=32 k-tiles, 8x8 register tile per thread (256 threads).
// SMEM pad = 34 floats/row: compute-read banks = (2*col + k) % 32 with lanes'
// cols differing by 1 -> 16 distinct banks, conflict-free.
// ---------------------------------------------------------------------------
#define BM  128
#define BN  128
#define BK  32
#define PAD 34

__global__ __launch_bounds__(256, 2)
void maxscore_kernel(const int* __restrict__ qmask, const int* __restrict__ dmask)
{
    __shared__ float sQ[BM * PAD];
    __shared__ float sD[BN * PAD];
    __shared__ float red[256];

    const int bb  = blockIdx.x;          // doc batch (0..63)
    const int by  = blockIdx.y;          // q row panel (0..15)
    const int tid = threadIdx.x;
    const int ty  = tid >> 4;            // 0..15
    const int tx  = tid & 15;            // 0..15
    const int rowb = ty * 8;             // thread's 8 rows: rowb..rowb+7

    float tmax = -1e30f;

    #pragma unroll 1
    for (int nt = 0; nt < 2; nt++) {
        float acc[8][8];
        #pragma unroll
        for (int i = 0; i < 8; i++)
            #pragma unroll
            for (int j = 0; j < 8; j++) acc[i][j] = 0.f;

        #pragma unroll 1
        for (int kt = 0; kt < 4; kt++) {
            // --- load Q tile: 128 rows x 32 k (float2 units: 2048, 8/thread)
            #pragma unroll
            for (int u = 0; u < 8; u++) {
                int lin = u * 256 + tid;
                int row = lin >> 4;          // 16 float2 per row
                int k2  = lin & 15;
                int frow = by * BM + row;    // flat q token (== q_mask index)
                float m = qmask[frow] ? 1.f : 0.f;
                float2 g = *(const float2*)(g_qn + frow * H + kt * BK + k2 * 2);
                *(float2*)(sQ + row * PAD + k2 * 2) = make_float2(g.x * m, g.y * m);
            }
            // --- load D tile: 128 rows x 32 k
            #pragma unroll
            for (int u = 0; u < 8; u++) {
                int lin = u * 256 + tid;
                int row = lin >> 4;
                int k2  = lin & 15;
                int ftok = bb * SD + nt * BN + row;   // flat d token (== d_mask index)
                float m = dmask[ftok] ? 1.f : 0.f;
                float2 g = *(const float2*)(g_dn + ftok * H + kt * BK + k2 * 2);
                *(float2*)(sD + row * PAD + k2 * 2) = make_float2(g.x * m, g.y * m);
            }
            __syncthreads();

            #pragma unroll 4
            for (int k = 0; k < BK; k++) {
                float qv[8], dv[8];
                #pragma unroll
                for (int i = 0; i < 8; i++) qv[i] = sQ[(rowb + i) * PAD + k];
                #pragma unroll
                for (int j = 0; j < 8; j++) dv[j] = sD[(j * 16 + tx) * PAD + k];
                #pragma unroll
                for (int i = 0; i < 8; i++)
                    #pragma unroll
                    for (int j = 0; j < 8; j++)
                        acc[i][j] = fmaf(qv[i], dv[j], acc[i][j]);
            }
            __syncthreads();
        }
        // fold this n-tile into the running max
        #pragma unroll
        for (int i = 0; i < 8; i++)
            #pragma unroll
            for (int j = 0; j < 8; j++) tmax = fmaxf(tmax, acc[i][j]);
    }

    // Thread's 8 rows (ty*8..ty*8+7) lie entirely inside a_local = ty>>2.
    // Threads [al*64, al*64+64) share the same (a, b): reduce in SMEM.
    red[tid] = tmax;
    __syncthreads();
    if (tid < 4) {
        float m = -1e30f;
        #pragma unroll 8
        for (int i = 0; i < 64; i++) m = fmaxf(m, red[tid * 64 + i]);
        g_scores[(by * 4 + tid) * NB + bb] = m;
    }
}

// ---------------------------------------------------------------------------
// Kernel 4: loss = mean_a( logsumexp(scores[a,:]) - scores[a,a]
//                          + avg_simq[a] + avg_simd[a] )
// (TEMPERATURE = 1, DIV_COEFF = 1)
// ---------------------------------------------------------------------------
__global__ void final_kernel(float* __restrict__ out)
{
    __shared__ float red[64];
    int a = threadIdx.x;   // 64 threads

    float m = -1e30f;
    #pragma unroll 8
    for (int j = 0; j < NB; j++) m = fmaxf(m, g_scores[a * NB + j]);
    float s = 0.f;
    #pragma unroll 8
    for (int j = 0; j < NB; j++) s += expf(g_scores[a * NB + j] - m);
    float lse = m + logf(s);

    red[a] = lse - g_scores[a * NB + a] + g_avgq[a] + g_avgd[a];
    __syncthreads();
    #pragma unroll
    for (int o = 32; o; o >>= 1) {
        if (a < o) red[a] += red[a + o];
        __syncthreads();
    }
    if (a == 0) out[0] = red[0] * (1.0f / NB);
}

// ---------------------------------------------------------------------------
extern "C" void kernel_launch(void* const* d_in, const int* in_sizes, int n_in,
                              void* d_out, int out_size)
{
    const float* q_emb  = (const float*)d_in[0];   // [64,32,128]
    const float* d_emb  = (const float*)d_in[1];   // [64,256,128]
    const int*   q_mask = (const int*)  d_in[2];   // [64,32]
    const int*   d_mask = (const int*)  d_in[3];   // [64,256]
    float*       out    = (float*)d_out;

    normalize_kernel<<<NQTOK / 8, 256>>>(q_emb, NQTOK, 0);
    normalize_kernel<<<NDTOK / 8, 256>>>(d_emb, NDTOK, 1);
    avgsim_kernel<<<NB, 128>>>();
    maxscore_kernel<<<dim3(NB, NQTOK / BM), 256>>>(q_mask, d_mask);
    final_kernel<<<1, 64>>>(out);
}

// round 3
// speedup vs baseline: 2.6727x; 2.6727x over previous
#include <cuda_runtime.h>
#include <math.h>
#include <stdint.h>

#define H    128
#define NB   64
#define SQ   32
#define SD   256
#define NQTOK (NB*SQ)   // 2048
#define NDTOK (NB*SD)   // 16384

// ---------------- scratch (allocation-free rule) ----------------
__device__ float g_qn[NQTOK*H];   // normalized q, f32, unmasked (avgsim)
__device__ float g_dn[NDTOK*H];   // normalized d, f32, unmasked (avgsim)
__device__ float g_qt[NQTOK*H];   // normalized q, masked, tf32-rounded (GEMM)
__device__ float g_dt[NDTOK*H];   // normalized d, masked, tf32-rounded (GEMM)
__device__ float g_part[2*NB*NB]; // per-d-half partial maxes
__device__ float g_avgq[NB];
__device__ float g_avgd[NB];

// ---------------- helpers ----------------
__device__ __forceinline__ uint32_t smem_u32(const void* p) {
    uint32_t a;
    asm("{ .reg .u64 t; cvta.to.shared.u64 t, %1; cvt.u32.u64 %0, t; }" : "=r"(a) : "l"(p));
    return a;
}
__device__ __forceinline__ float f2tf32(float x) {
    uint32_t r;
    asm("cvt.rna.tf32.f32 %0, %1;" : "=r"(r) : "f"(x));
    return __uint_as_float(r);
}
__device__ __forceinline__ void mma_tf32(float& d0, float& d1, float& d2, float& d3,
                                         uint32_t a0, uint32_t a1, uint32_t a2, uint32_t a3,
                                         uint32_t b0, uint32_t b1) {
    asm volatile("mma.sync.aligned.m16n8k8.row.col.f32.tf32.tf32.f32 "
                 "{%0,%1,%2,%3}, {%4,%5,%6,%7}, {%8,%9}, {%0,%1,%2,%3};"
                 : "+f"(d0), "+f"(d1), "+f"(d2), "+f"(d3)
                 : "r"(a0), "r"(a1), "r"(a2), "r"(a3), "r"(b0), "r"(b1));
}
#define CP_ASYNC16(dst, src) \
    asm volatile("cp.async.cg.shared.global [%0], [%1], 16;" :: "r"(dst), "l"(src))
#define CP_COMMIT() asm volatile("cp.async.commit_group;" ::: "memory")
#define CP_WAIT0()  asm volatile("cp.async.wait_group 0;" ::: "memory")

// ---------------------------------------------------------------------------
// Kernel 1: normalize; write unmasked f32 (avgsim) + masked tf32 (GEMM).
// One warp per token, float4 per lane.
// ---------------------------------------------------------------------------
__global__ void normsplit_kernel(const float* __restrict__ in, const int* __restrict__ mask,
                                 int ntok, float* __restrict__ outf, float* __restrict__ outt)
{
    int wid  = threadIdx.x >> 5;
    int lane = threadIdx.x & 31;
    int tok  = blockIdx.x * 8 + wid;
    if (tok >= ntok) return;

    float4 v = ((const float4*)in)[tok * 32 + lane];
    float ss = v.x*v.x + v.y*v.y + v.z*v.z + v.w*v.w;
    #pragma unroll
    for (int o = 16; o; o >>= 1) ss += __shfl_xor_sync(0xffffffffu, ss, o);
    float scale = 1.0f / fmaxf(sqrtf(ss), 1e-12f);
    v.x *= scale; v.y *= scale; v.z *= scale; v.w *= scale;

    ((float4*)outf)[tok * 32 + lane] = v;   // unmasked f32

    float m = mask[tok] ? 1.0f : 0.0f;
    float4 t;
    t.x = f2tf32(v.x * m); t.y = f2tf32(v.y * m);
    t.z = f2tf32(v.z * m); t.w = f2tf32(v.w * m);
    ((float4*)outt)[tok * 32 + lane] = t;
}

// ---------------------------------------------------------------------------
// Kernel 2: avg off-diagonal pairwise sim via ||sum||^2 - sum||.||^2
// ---------------------------------------------------------------------------
__global__ void avgsim_kernel()
{
    int b = blockIdx.x;
    int h = threadIdx.x;
    __shared__ float r1[128], r2[128];

    float sum = 0.f, ss = 0.f;
    #pragma unroll 4
    for (int s = 0; s < SQ; s++) { float v = g_qn[(b*SQ + s)*H + h]; sum += v; ss += v*v; }
    r1[h] = sum * sum;  r2[h] = ss;
    __syncthreads();
    #pragma unroll
    for (int o = 64; o; o >>= 1) { if (h < o) { r1[h] += r1[h+o]; r2[h] += r2[h+o]; } __syncthreads(); }
    if (h == 0) g_avgq[b] = (r1[0] - r2[0]) * (1.0f / (SQ * (SQ - 1)));
    __syncthreads();

    sum = 0.f; ss = 0.f;
    #pragma unroll 4
    for (int s = 0; s < SD; s++) { float v = g_dn[(b*SD + s)*H + h]; sum += v; ss += v*v; }
    r1[h] = sum * sum;  r2[h] = ss;
    __syncthreads();
    #pragma unroll
    for (int o = 64; o; o >>= 1) { if (h < o) { r1[h] += r1[h+o]; r2[h] += r2[h+o]; } __syncthreads(); }
    if (h == 0) g_avgd[b] = (r1[0] - r2[0]) * (1.0f / ((float)SD * (SD - 1)));
}

// ---------------------------------------------------------------------------
// Kernel 3: persistent tf32 mma.sync max-GEMM.
// 128 CTAs: CTA ct owns D rows [ct*128, ct*128+128) (b = ct>>1), loops over
// all 16 Q panels (double-buffered cp.async). 4 warps, 64x64 warp tiles,
// m16n8k8 tf32 MMA, max-epilogue -> g_part[ct&1][a][b].
// ---------------------------------------------------------------------------
#define STRIDE 132                       // floats per smem row (pad -> conflict-free)
#define TILE_FLOATS (128*STRIDE)
#define SMEM_BYTES (3*TILE_FLOATS*4 + 64)

// cp.async one 128x128 f32 tile (gmem row-major, stride 128) into smem (STRIDE).
__device__ __forceinline__ void cp_tile(float* dst, const float* __restrict__ src, int tid)
{
    #pragma unroll
    for (int i = 0; i < 32; i++) {
        int idx = i * 128 + tid;
        int row = idx >> 5;
        int sl  = idx & 31;
        uint32_t d = smem_u32(dst + row * STRIDE + sl * 4);
        CP_ASYNC16(d, src + row * 128 + sl * 4);
    }
}

__global__ __launch_bounds__(128, 1) void maxgemm_kernel()
{
    extern __shared__ float sm[];
    float* sD   = sm;                    // 128 x STRIDE
    float* sQ0  = sm + TILE_FLOATS;
    float* sQ1  = sm + 2 * TILE_FLOATS;
    float* sred = sm + 3 * TILE_FLOATS; // 8 floats

    const int ct   = blockIdx.x;        // 0..127
    const int tid  = threadIdx.x;       // 128 threads
    const int wid  = tid >> 5;
    const int lane = tid & 31;
    const int g    = lane >> 2;         // group id 0..7
    const int t    = lane & 3;          // thread-in-group
    const int wm   = wid >> 1;          // warp m (0..1)
    const int wn   = wid & 1;           // warp n (0..1)

    // prolog: D tile + Q panel 0
    cp_tile(sD,  g_dt + ct * 128 * H, tid);
    cp_tile(sQ0, g_qt,                tid);
    CP_COMMIT();
    CP_WAIT0();
    __syncthreads();

    const uint32_t* uD = (const uint32_t*)sD;

    #pragma unroll 1
    for (int p = 0; p < 16; p++) {
        float* cur = (p & 1) ? sQ1 : sQ0;
        float* nxt = (p & 1) ? sQ0 : sQ1;
        if (p < 15) {
            cp_tile(nxt, g_qt + (p + 1) * 128 * H, tid);
            CP_COMMIT();
        }
        const uint32_t* uQ = (const uint32_t*)cur;

        float acc[4][8][4];
        #pragma unroll
        for (int mt = 0; mt < 4; mt++)
            #pragma unroll
            for (int nt = 0; nt < 8; nt++)
                #pragma unroll
                for (int r = 0; r < 4; r++) acc[mt][nt][r] = 0.f;

        #pragma unroll
        for (int s = 0; s < 16; s++) {
            const int k0 = 8 * s + t;
            uint32_t A[4][4];
            #pragma unroll
            for (int mt = 0; mt < 4; mt++) {
                int r0 = (wm * 64 + mt * 16 + g) * STRIDE;
                A[mt][0] = uQ[r0 + k0];
                A[mt][1] = uQ[r0 + 8 * STRIDE + k0];
                A[mt][2] = uQ[r0 + k0 + 4];
                A[mt][3] = uQ[r0 + 8 * STRIDE + k0 + 4];
            }
            uint32_t B[8][2];
            #pragma unroll
            for (int nt = 0; nt < 8; nt++) {
                int c0 = (wn * 64 + nt * 8 + g) * STRIDE;
                B[nt][0] = uD[c0 + k0];
                B[nt][1] = uD[c0 + k0 + 4];
            }
            #pragma unroll
            for (int mt = 0; mt < 4; mt++)
                #pragma unroll
                for (int nt = 0; nt < 8; nt++)
                    mma_tf32(acc[mt][nt][0], acc[mt][nt][1], acc[mt][nt][2], acc[mt][nt][3],
                             A[mt][0], A[mt][1], A[mt][2], A[mt][3],
                             B[nt][0], B[nt][1]);
        }

        // ---- epilogue: per-(a, b) max ----
        float m0 = -1e30f, m1 = -1e30f;   // mt<2 -> a_sub 0, mt>=2 -> a_sub 1
        #pragma unroll
        for (int mt = 0; mt < 4; mt++) {
            float mm = -1e30f;
            #pragma unroll
            for (int nt = 0; nt < 8; nt++)
                #pragma unroll
                for (int r = 0; r < 4; r++) mm = fmaxf(mm, acc[mt][nt][r]);
            if (mt < 2) m0 = fmaxf(m0, mm); else m1 = fmaxf(m1, mm);
        }
        #pragma unroll
        for (int o = 16; o; o >>= 1) {
            m0 = fmaxf(m0, __shfl_xor_sync(0xffffffffu, m0, o));
            m1 = fmaxf(m1, __shfl_xor_sync(0xffffffffu, m1, o));
        }
        if (lane == 0) {
            sred[(wm * 2 + 0) * 2 + wn] = m0;
            sred[(wm * 2 + 1) * 2 + wn] = m1;
        }
        __syncthreads();
        if (tid < 4) {
            float v = fmaxf(sred[tid * 2], sred[tid * 2 + 1]);
            // a = p*4 + tid ; b = ct>>1 ; half = ct&1
            g_part[(ct & 1) * (NB * NB) + (p * 4 + tid) * NB + (ct >> 1)] = v;
        }
        if (p < 15) CP_WAIT0();
        __syncthreads();
    }
}

// ---------------------------------------------------------------------------
// Kernel 4: combine halves; loss = mean_a( lse - diag + avgq + avgd )
// ---------------------------------------------------------------------------
__global__ void final_kernel(float* __restrict__ out)
{
    __shared__ float red[64];
    __shared__ float srow[64];
    int a = threadIdx.x;

    float m = -1e30f;
    #pragma unroll 8
    for (int j = 0; j < NB; j++) {
        float v = fmaxf(g_part[a * NB + j], g_part[NB * NB + a * NB + j]);
        srow[j] = 0.f;   // placeholder write to keep srow resident (unused value)
        m = fmaxf(m, v);
    }
    float s = 0.f;
    float diag = 0.f;
    #pragma unroll 8
    for (int j = 0; j < NB; j++) {
        float v = fmaxf(g_part[a * NB + j], g_part[NB * NB + a * NB + j]);
        if (j == a) diag = v;
        s += expf(v - m);
    }
    float lse = m + logf(s);

    red[a] = lse - diag + g_avgq[a] + g_avgd[a];
    __syncthreads();
    #pragma unroll
    for (int o = 32; o; o >>= 1) { if (a < o) red[a] += red[a + o]; __syncthreads(); }
    if (a == 0) out[0] = red[0] * (1.0f / NB);
}

// ---------------------------------------------------------------------------
extern "C" void kernel_launch(void* const* d_in, const int* in_sizes, int n_in,
                              void* d_out, int out_size)
{
    const float* q_emb  = (const float*)d_in[0];
    const float* d_emb  = (const float*)d_in[1];
    const int*   q_mask = (const int*)  d_in[2];
    const int*   d_mask = (const int*)  d_in[3];
    float*       out    = (float*)d_out;

    cudaFuncSetAttribute(maxgemm_kernel,
                         cudaFuncAttributeMaxDynamicSharedMemorySize, SMEM_BYTES);

    float *qn, *dn, *qt, *dt;
    cudaGetSymbolAddress((void**)&qn, g_qn);
    cudaGetSymbolAddress((void**)&dn, g_dn);
    cudaGetSymbolAddress((void**)&qt, g_qt);
    cudaGetSymbolAddress((void**)&dt, g_dt);

    normsplit_kernel<<<NQTOK / 8, 256>>>(q_emb, q_mask, NQTOK, qn, qt);
    normsplit_kernel<<<NDTOK / 8, 256>>>(d_emb, d_mask, NDTOK, dn, dt);
    avgsim_kernel<<<NB, 128>>>();
    maxgemm_kernel<<<128, 128, SMEM_BYTES>>>();
    final_kernel<<<1, 64>>>(out);
}

// round 4
// speedup vs baseline: 3.5195x; 1.3168x over previous
#include <cuda_runtime.h>
#include <math.h>
#include <stdint.h>

#define H    128
#define NB   64
#define SQ   32
#define SD   256
#define NQTOK (NB*SQ)   // 2048
#define NDTOK (NB*SD)   // 16384

// ---------------- scratch (allocation-free rule) ----------------
__device__ float g_qt[NQTOK*H];   // normalized q, masked, tf32-rounded
__device__ float g_dt[NDTOK*H];   // normalized d, masked, tf32-rounded
__device__ float g_sumq[NB*H];    // per-batch sum of unmasked normalized q tokens
__device__ float g_sumd[NB*H];
__device__ float g_scores[NB*NB];

// ---------------- helpers ----------------
__device__ __forceinline__ uint32_t smem_u32(const void* p) {
    uint32_t a;
    asm("{ .reg .u64 t; cvta.to.shared.u64 t, %1; cvt.u32.u64 %0, t; }" : "=r"(a) : "l"(p));
    return a;
}
__device__ __forceinline__ float f2tf32(float x) {
    uint32_t r;
    asm("cvt.rna.tf32.f32 %0, %1;" : "=r"(r) : "f"(x));
    return __uint_as_float(r);
}
__device__ __forceinline__ void mma_tf32(float& d0, float& d1, float& d2, float& d3,
                                         uint32_t a0, uint32_t a1, uint32_t a2, uint32_t a3,
                                         uint32_t b0, uint32_t b1) {
    asm volatile("mma.sync.aligned.m16n8k8.row.col.f32.tf32.tf32.f32 "
                 "{%0,%1,%2,%3}, {%4,%5,%6,%7}, {%8,%9}, {%0,%1,%2,%3};"
                 : "+f"(d0), "+f"(d1), "+f"(d2), "+f"(d3)
                 : "r"(a0), "r"(a1), "r"(a2), "r"(a3), "r"(b0), "r"(b1));
}
#define CP_ASYNC16(dst, src) \
    asm volatile("cp.async.cg.shared.global [%0], [%1], 16;" :: "r"(dst), "l"(src))
#define CP_COMMIT() asm volatile("cp.async.commit_group;" ::: "memory")
#define CP_WAIT0()  asm volatile("cp.async.wait_group 0;" ::: "memory")

// ---------------------------------------------------------------------------
// Kernel 1: normalize + mask + tf32 round; accumulate unmasked per-batch sums.
// 8 warps = 8 tokens per block; all 8 tokens belong to the same batch
// (tokens_per_batch is a multiple of 8 for both q=32 and d=256).
// ---------------------------------------------------------------------------
__global__ void normsplit_kernel(const float* __restrict__ in, const int* __restrict__ mask,
                                 int tpb, float* __restrict__ outt, float* __restrict__ sums)
{
    __shared__ float red[8 * 128];
    int tid  = threadIdx.x;
    int wid  = tid >> 5;
    int lane = tid & 31;
    int tok  = blockIdx.x * 8 + wid;

    float4 v = ((const float4*)in)[tok * 32 + lane];
    float ss = v.x*v.x + v.y*v.y + v.z*v.z + v.w*v.w;
    #pragma unroll
    for (int o = 16; o; o >>= 1) ss += __shfl_xor_sync(0xffffffffu, ss, o);
    float scale = 1.0f / fmaxf(sqrtf(ss), 1e-12f);
    v.x *= scale; v.y *= scale; v.z *= scale; v.w *= scale;

    // stash unmasked normalized token for the batch-sum reduction
    red[wid * 128 + lane * 4 + 0] = v.x;
    red[wid * 128 + lane * 4 + 1] = v.y;
    red[wid * 128 + lane * 4 + 2] = v.z;
    red[wid * 128 + lane * 4 + 3] = v.w;

    float m = mask[tok] ? 1.0f : 0.0f;
    float4 t;
    t.x = f2tf32(v.x * m); t.y = f2tf32(v.y * m);
    t.z = f2tf32(v.z * m); t.w = f2tf32(v.w * m);
    ((float4*)outt)[tok * 32 + lane] = t;

    __syncthreads();
    if (tid < 128) {
        float s = 0.f;
        #pragma unroll
        for (int w = 0; w < 8; w++) s += red[w * 128 + tid];
        int b = (blockIdx.x * 8) / tpb;
        atomicAdd(&sums[b * 128 + tid], s);
    }
}

// ---------------------------------------------------------------------------
// Kernel 2: persistent tf32 max-GEMM.
// Grid (16, 8): CTA = (q panel p: 128 rows, d slice s: 2048 rows).
// Q panel full-K resident in SMEM; D streamed as K-half tiles (256 rows x 64 K),
// double-buffered cp.async. 8 warps, 64x64 warp tiles, m16n8k8 tf32.
// Each d subtile t = exactly batch b = s*8+t -> scores written directly.
// ---------------------------------------------------------------------------
#define QSTRIDE 132
#define DSTRIDE 68
#define Q_FLOATS  (128 * QSTRIDE)   // 16896
#define DH_FLOATS (256 * DSTRIDE)   // 17408
#define SMEM_BYTES ((Q_FLOATS + 2 * DH_FLOATS + 16) * 4)   // 206912 B

__device__ __forceinline__ void cp_qtile(float* dst, const float* __restrict__ src, int tid)
{
    #pragma unroll
    for (int i = 0; i < 16; i++) {
        int id  = i * 256 + tid;       // 4096 chunks of 16B
        int row = id >> 5;
        int ck  = id & 31;
        uint32_t d = smem_u32(dst + row * QSTRIDE + ck * 4);
        CP_ASYNC16(d, src + row * 128 + ck * 4);
    }
}
__device__ __forceinline__ void cp_dhalf(float* dst, const float* __restrict__ src_base,
                                         int kh, int tid)
{
    #pragma unroll
    for (int i = 0; i < 16; i++) {
        int id  = i * 256 + tid;       // 4096 chunks: 256 rows x 16 chunks
        int row = id >> 4;
        int ck  = id & 15;
        uint32_t d = smem_u32(dst + row * DSTRIDE + ck * 4);
        CP_ASYNC16(d, src_base + row * 128 + kh * 64 + ck * 4);
    }
}

__global__ __launch_bounds__(256, 1) void maxgemm_kernel()
{
    extern __shared__ float sm[];
    float* sQ   = sm;
    float* sB0  = sm + Q_FLOATS;
    float* sB1  = sm + Q_FLOATS + DH_FLOATS;
    float* sred = sm + Q_FLOATS + 2 * DH_FLOATS;   // 16 floats

    const int p    = blockIdx.x;     // q panel 0..15
    const int s    = blockIdx.y;     // d slice 0..7
    const int tid  = threadIdx.x;    // 256
    const int wid  = tid >> 5;
    const int lane = tid & 31;
    const int g    = lane >> 2;      // 0..7
    const int tg   = lane & 3;       // 0..3
    const int wm   = wid >> 2;       // 0..1 (64 q rows)
    const int wn   = wid & 3;        // 0..3 (64 d cols)

    const float* dbase = g_dt + (size_t)(s * 8) * 256 * H;

    // prolog: Q panel + first D half
    cp_qtile(sQ, g_qt + (size_t)p * 128 * H, tid);
    cp_dhalf(sB0, dbase, 0, tid);
    CP_COMMIT();
    CP_WAIT0();
    __syncthreads();

    const uint32_t* uQ = (const uint32_t*)sQ;

    #pragma unroll 1
    for (int t = 0; t < 8; t++) {
        float acc[4][8][4];
        #pragma unroll
        for (int mt = 0; mt < 4; mt++)
            #pragma unroll
            for (int nt = 0; nt < 8; nt++)
                #pragma unroll
                for (int r = 0; r < 4; r++) acc[mt][nt][r] = 0.f;

        #pragma unroll
        for (int kh = 0; kh < 2; kh++) {
            const int idx = t * 2 + kh;
            if (idx + 1 < 16) {
                int nt2 = (idx + 1) >> 1, nk = (idx + 1) & 1;
                cp_dhalf(((idx + 1) & 1) ? sB1 : sB0,
                         dbase + (size_t)nt2 * 256 * H, nk, tid);
                CP_COMMIT();
            }
            const uint32_t* uB = (const uint32_t*)((idx & 1) ? sB1 : sB0);
            const int kbase = kh * 64;

            #pragma unroll
            for (int ks = 0; ks < 8; ks++) {
                const int kq = kbase + 8 * ks + tg;
                const int kd = 8 * ks + tg;
                uint32_t A[4][4];
                #pragma unroll
                for (int mt = 0; mt < 4; mt++) {
                    int r0 = (wm * 64 + mt * 16 + g) * QSTRIDE;
                    A[mt][0] = uQ[r0 + kq];
                    A[mt][1] = uQ[r0 + 8 * QSTRIDE + kq];
                    A[mt][2] = uQ[r0 + kq + 4];
                    A[mt][3] = uQ[r0 + 8 * QSTRIDE + kq + 4];
                }
                uint32_t B[8][2];
                #pragma unroll
                for (int nt = 0; nt < 8; nt++) {
                    int c0 = (wn * 64 + nt * 8 + g) * DSTRIDE;
                    B[nt][0] = uB[c0 + kd];
                    B[nt][1] = uB[c0 + kd + 4];
                }
                #pragma unroll
                for (int mt = 0; mt < 4; mt++)
                    #pragma unroll
                    for (int nt = 0; nt < 8; nt++)
                        mma_tf32(acc[mt][nt][0], acc[mt][nt][1], acc[mt][nt][2], acc[mt][nt][3],
                                 A[mt][0], A[mt][1], A[mt][2], A[mt][3],
                                 B[nt][0], B[nt][1]);
            }
            CP_WAIT0();
            __syncthreads();
        }

        // ---- epilogue: this d subtile is exactly batch b = s*8+t ----
        // warp rows wm*64..wm*64+63 = a_locals {wm*2, wm*2+1}
        float m0 = -1e30f, m1 = -1e30f;
        #pragma unroll
        for (int mt = 0; mt < 4; mt++) {
            float mm = -1e30f;
            #pragma unroll
            for (int nt = 0; nt < 8; nt++)
                #pragma unroll
                for (int r = 0; r < 4; r++) mm = fmaxf(mm, acc[mt][nt][r]);
            if (mt < 2) m0 = fmaxf(m0, mm); else m1 = fmaxf(m1, mm);
        }
        #pragma unroll
        for (int o = 16; o; o >>= 1) {
            m0 = fmaxf(m0, __shfl_xor_sync(0xffffffffu, m0, o));
            m1 = fmaxf(m1, __shfl_xor_sync(0xffffffffu, m1, o));
        }
        if (lane == 0) {
            sred[(wm * 2 + 0) * 4 + wn] = m0;
            sred[(wm * 2 + 1) * 4 + wn] = m1;
        }
        __syncthreads();
        if (tid < 4) {
            float v = fmaxf(fmaxf(sred[tid * 4 + 0], sred[tid * 4 + 1]),
                            fmaxf(sred[tid * 4 + 2], sred[tid * 4 + 3]));
            g_scores[(p * 4 + tid) * NB + (s * 8 + t)] = v;
        }
        __syncthreads();
    }
}

// ---------------------------------------------------------------------------
// Kernel 3: finish. avg_sim via (||sum||^2 - S)/(S*(S-1)) (unit-norm tokens),
// then loss = mean_a( lse(scores[a,:]) - scores[a,a] + avgq[a] + avgd[a] ).
// ---------------------------------------------------------------------------
__global__ void final_kernel(float* __restrict__ out)
{
    __shared__ float savgq[64], savgd[64], red[64];
    int tid  = threadIdx.x;   // 256
    int wid  = tid >> 5;
    int lane = tid & 31;

    for (int b = wid; b < NB; b += 8) {
        float4 vq = ((const float4*)g_sumq)[b * 32 + lane];
        float4 vd = ((const float4*)g_sumd)[b * 32 + lane];
        float sq = vq.x*vq.x + vq.y*vq.y + vq.z*vq.z + vq.w*vq.w;
        float sd = vd.x*vd.x + vd.y*vd.y + vd.z*vd.z + vd.w*vd.w;
        #pragma unroll
        for (int o = 16; o; o >>= 1) {
            sq += __shfl_xor_sync(0xffffffffu, sq, o);
            sd += __shfl_xor_sync(0xffffffffu, sd, o);
        }
        if (lane == 0) {
            savgq[b] = (sq - (float)SQ) * (1.0f / ((float)SQ * (SQ - 1)));
            savgd[b] = (sd - (float)SD) * (1.0f / ((float)SD * (SD - 1)));
        }
    }
    __syncthreads();

    if (tid < NB) {
        int a = tid;
        float m = -1e30f;
        #pragma unroll 8
        for (int j = 0; j < NB; j++) m = fmaxf(m, g_scores[a * NB + j]);
        float ssum = 0.f;
        #pragma unroll 8
        for (int j = 0; j < NB; j++) ssum += expf(g_scores[a * NB + j] - m);
        float lse = m + logf(ssum);
        red[a] = lse - g_scores[a * NB + a] + savgq[a] + savgd[a];
    }
    __syncthreads();
    if (tid < 32) {
        float v = red[tid] + red[tid + 32];
        #pragma unroll
        for (int o = 16; o; o >>= 1) v += __shfl_xor_sync(0xffffffffu, v, o);
        if (tid == 0) out[0] = v * (1.0f / NB);
    }
}

// ---------------------------------------------------------------------------
extern "C" void kernel_launch(void* const* d_in, const int* in_sizes, int n_in,
                              void* d_out, int out_size)
{
    const float* q_emb  = (const float*)d_in[0];
    const float* d_emb  = (const float*)d_in[1];
    const int*   q_mask = (const int*)  d_in[2];
    const int*   d_mask = (const int*)  d_in[3];
    float*       out    = (float*)d_out;

    cudaFuncSetAttribute(maxgemm_kernel,
                         cudaFuncAttributeMaxDynamicSharedMemorySize, SMEM_BYTES);

    float *qt, *dt, *sumq, *sumd;
    cudaGetSymbolAddress((void**)&qt, g_qt);
    cudaGetSymbolAddress((void**)&dt, g_dt);
    cudaGetSymbolAddress((void**)&sumq, g_sumq);
    cudaGetSymbolAddress((void**)&sumd, g_sumd);

    cudaMemsetAsync(sumq, 0, NB * H * sizeof(float));
    cudaMemsetAsync(sumd, 0, NB * H * sizeof(float));
    normsplit_kernel<<<NQTOK / 8, 256>>>(q_emb, q_mask, SQ, qt, sumq);
    normsplit_kernel<<<NDTOK / 8, 256>>>(d_emb, d_mask, SD, dt, sumd);
    maxgemm_kernel<<<dim3(16, 8), 256, SMEM_BYTES>>>();
    final_kernel<<<1, 256>>>(out);
}

// round 5
// speedup vs baseline: 3.6636x; 1.0409x over previous
#include <cuda_runtime.h>
#include <math.h>
#include <stdint.h>

#define H    128
#define NB   64
#define SQ   32
#define SD   256
#define NQTOK (NB*SQ)   // 2048
#define NDTOK (NB*SD)   // 16384

// ---------------- scratch (allocation-free rule) ----------------
__device__ float g_qt[NQTOK*H];   // normalized q, masked, tf32-rounded
__device__ float g_dt[NDTOK*H];   // normalized d, masked, tf32-rounded
__device__ float g_sumq[NB*H];    // per-batch sum of unmasked normalized q tokens
__device__ float g_sumd[NB*H];
__device__ float g_scores[NB*NB];
__device__ unsigned g_done;       // zero-init; last CTA resets -> replay-safe

// ---------------- helpers ----------------
__device__ __forceinline__ uint32_t smem_u32(const void* p) {
    uint32_t a;
    asm("{ .reg .u64 t; cvta.to.shared.u64 t, %1; cvt.u32.u64 %0, t; }" : "=r"(a) : "l"(p));
    return a;
}
__device__ __forceinline__ float f2tf32(float x) {
    uint32_t r;
    asm("cvt.rna.tf32.f32 %0, %1;" : "=r"(r) : "f"(x));
    return __uint_as_float(r);
}
__device__ __forceinline__ void mma_tf32(float& d0, float& d1, float& d2, float& d3,
                                         uint32_t a0, uint32_t a1, uint32_t a2, uint32_t a3,
                                         uint32_t b0, uint32_t b1) {
    asm volatile("mma.sync.aligned.m16n8k8.row.col.f32.tf32.tf32.f32 "
                 "{%0,%1,%2,%3}, {%4,%5,%6,%7}, {%8,%9}, {%0,%1,%2,%3};"
                 : "+f"(d0), "+f"(d1), "+f"(d2), "+f"(d3)
                 : "r"(a0), "r"(a1), "r"(a2), "r"(a3), "r"(b0), "r"(b1));
}
#define CP_ASYNC16(dst, src) \
    asm volatile("cp.async.cg.shared.global [%0], [%1], 16;" :: "r"(dst), "l"(src))
#define CP_COMMIT() asm volatile("cp.async.commit_group;" ::: "memory")
#define CP_WAIT0()  asm volatile("cp.async.wait_group 0;" ::: "memory")

// ---------------------------------------------------------------------------
// Kernel 1: normalize + mask + tf32 round + per-batch unmasked sums (atomics).
// Merged q+d: blocks [0,256) = q tokens, [256, 2304) = d tokens.
// 8 warps = 8 tokens per block (one batch per block: tpb % 8 == 0).
// ---------------------------------------------------------------------------
__global__ void normsplit_all(const float* __restrict__ qin, const float* __restrict__ din,
                              const int* __restrict__ qm, const int* __restrict__ dm)
{
    __shared__ float red[8 * 128];
    const int blk  = blockIdx.x;
    const int tid  = threadIdx.x;
    const int wid  = tid >> 5;
    const int lane = tid & 31;

    const float* in;  const int* mask;  float* outt;  float* sums;  int tpb, tokbase;
    if (blk < 256) { in = qin; mask = qm; outt = g_qt; sums = g_sumq; tpb = SQ; tokbase = blk * 8; }
    else           { in = din; mask = dm; outt = g_dt; sums = g_sumd; tpb = SD; tokbase = (blk - 256) * 8; }

    const int tok = tokbase + wid;
    float4 v = ((const float4*)in)[tok * 32 + lane];
    float ss = v.x*v.x + v.y*v.y + v.z*v.z + v.w*v.w;
    #pragma unroll
    for (int o = 16; o; o >>= 1) ss += __shfl_xor_sync(0xffffffffu, ss, o);
    float scale = 1.0f / fmaxf(sqrtf(ss), 1e-12f);
    v.x *= scale; v.y *= scale; v.z *= scale; v.w *= scale;

    red[wid * 128 + lane * 4 + 0] = v.x;
    red[wid * 128 + lane * 4 + 1] = v.y;
    red[wid * 128 + lane * 4 + 2] = v.z;
    red[wid * 128 + lane * 4 + 3] = v.w;

    float m = mask[tok] ? 1.0f : 0.0f;
    float4 t;
    t.x = f2tf32(v.x * m); t.y = f2tf32(v.y * m);
    t.z = f2tf32(v.z * m); t.w = f2tf32(v.w * m);
    ((float4*)outt)[tok * 32 + lane] = t;

    __syncthreads();
    if (tid < 128) {
        float s = 0.f;
        #pragma unroll
        for (int w = 0; w < 8; w++) s += red[w * 128 + tid];
        atomicAdd(&sums[(tokbase / tpb) * 128 + tid], s);
    }
}

// ---------------------------------------------------------------------------
// Kernel 2: tf32 max-GEMM + fused final loss (last-CTA pattern).
// Grid (16, 8): CTA = (q panel p: 128 rows, d slice s: 8 batches x 256 rows).
// Q panel full-K resident; D streamed as double-buffered K-half tiles.
// 8 warps, 64x64 warp tiles, m16n8k8 tf32.
// ---------------------------------------------------------------------------
#define QSTRIDE 132
#define DSTRIDE 68
#define Q_FLOATS  (128 * QSTRIDE)
#define DH_FLOATS (256 * DSTRIDE)
#define SMEM_BYTES ((Q_FLOATS + 2 * DH_FLOATS + 16 * 8) * 4)

__device__ __forceinline__ void cp_qtile(float* dst, const float* __restrict__ src, int tid)
{
    #pragma unroll
    for (int i = 0; i < 16; i++) {
        int id  = i * 256 + tid;
        int row = id >> 5;
        int ck  = id & 31;
        uint32_t d = smem_u32(dst + row * QSTRIDE + ck * 4);
        CP_ASYNC16(d, src + row * 128 + ck * 4);
    }
}
__device__ __forceinline__ void cp_dhalf(float* dst, const float* __restrict__ src_base,
                                         int kh, int tid)
{
    #pragma unroll
    for (int i = 0; i < 16; i++) {
        int id  = i * 256 + tid;
        int row = id >> 4;
        int ck  = id & 15;
        uint32_t d = smem_u32(dst + row * DSTRIDE + ck * 4);
        CP_ASYNC16(d, src_base + row * 128 + kh * 64 + ck * 4);
    }
}

__global__ __launch_bounds__(256, 1) void maxgemm_kernel(float* __restrict__ out)
{
    extern __shared__ float sm[];
    float* sQ   = sm;
    float* sB0  = sm + Q_FLOATS;
    float* sB1  = sm + Q_FLOATS + DH_FLOATS;
    float* sred = sm + Q_FLOATS + 2 * DH_FLOATS;   // 16 floats x 8 subtiles

    __shared__ bool  s_last;
    __shared__ float s_avgq[64], s_avgd[64], s_red[64];

    const int p    = blockIdx.x;     // q panel 0..15
    const int s    = blockIdx.y;     // d slice 0..7
    const int tid  = threadIdx.x;    // 256
    const int wid  = tid >> 5;
    const int lane = tid & 31;
    const int g    = lane >> 2;
    const int tg   = lane & 3;
    const int wm   = wid >> 2;       // 0..1
    const int wn   = wid & 3;        // 0..3

    const float* dbase = g_dt + (size_t)(s * 8) * 256 * H;

    cp_qtile(sQ, g_qt + (size_t)p * 128 * H, tid);
    cp_dhalf(sB0, dbase, 0, tid);
    CP_COMMIT();
    CP_WAIT0();
    __syncthreads();

    const uint32_t* uQ = (const uint32_t*)sQ;

    #pragma unroll 1
    for (int t = 0; t < 8; t++) {
        float acc[4][8][4];
        #pragma unroll
        for (int mt = 0; mt < 4; mt++)
            #pragma unroll
            for (int nt = 0; nt < 8; nt++)
                #pragma unroll
                for (int r = 0; r < 4; r++) acc[mt][nt][r] = 0.f;

        #pragma unroll
        for (int kh = 0; kh < 2; kh++) {
            const int idx = t * 2 + kh;
            if (idx + 1 < 16) {
                int nt2 = (idx + 1) >> 1, nk = (idx + 1) & 1;
                cp_dhalf(((idx + 1) & 1) ? sB1 : sB0,
                         dbase + (size_t)nt2 * 256 * H, nk, tid);
                CP_COMMIT();
            }
            const uint32_t* uB = (const uint32_t*)((idx & 1) ? sB1 : sB0);
            const int kbase = kh * 64;

            #pragma unroll
            for (int ks = 0; ks < 8; ks++) {
                const int kq = kbase + 8 * ks + tg;
                const int kd = 8 * ks + tg;
                uint32_t A[4][4];
                #pragma unroll
                for (int mt = 0; mt < 4; mt++) {
                    int r0 = (wm * 64 + mt * 16 + g) * QSTRIDE;
                    A[mt][0] = uQ[r0 + kq];
                    A[mt][1] = uQ[r0 + 8 * QSTRIDE + kq];
                    A[mt][2] = uQ[r0 + kq + 4];
                    A[mt][3] = uQ[r0 + 8 * QSTRIDE + kq + 4];
                }
                uint32_t B[8][2];
                #pragma unroll
                for (int nt = 0; nt < 8; nt++) {
                    int c0 = (wn * 64 + nt * 8 + g) * DSTRIDE;
                    B[nt][0] = uB[c0 + kd];
                    B[nt][1] = uB[c0 + kd + 4];
                }
                #pragma unroll
                for (int mt = 0; mt < 4; mt++)
                    #pragma unroll
                    for (int nt = 0; nt < 8; nt++)
                        mma_tf32(acc[mt][nt][0], acc[mt][nt][1], acc[mt][nt][2], acc[mt][nt][3],
                                 A[mt][0], A[mt][1], A[mt][2], A[mt][3],
                                 B[nt][0], B[nt][1]);
            }
            CP_WAIT0();
            __syncthreads();
        }

        // ---- epilogue: subtile t = batch b = s*8+t ----
        float m0 = -1e30f, m1 = -1e30f;
        #pragma unroll
        for (int mt = 0; mt < 4; mt++) {
            float mm = -1e30f;
            #pragma unroll
            for (int nt = 0; nt < 8; nt++)
                #pragma unroll
                for (int r = 0; r < 4; r++) mm = fmaxf(mm, acc[mt][nt][r]);
            if (mt < 2) m0 = fmaxf(m0, mm); else m1 = fmaxf(m1, mm);
        }
        #pragma unroll
        for (int o = 16; o; o >>= 1) {
            m0 = fmaxf(m0, __shfl_xor_sync(0xffffffffu, m0, o));
            m1 = fmaxf(m1, __shfl_xor_sync(0xffffffffu, m1, o));
        }
        if (lane == 0) {
            sred[t * 16 + (wm * 2 + 0) * 4 + wn] = m0;
            sred[t * 16 + (wm * 2 + 1) * 4 + wn] = m1;
        }
    }

    __syncthreads();
    if (tid < 32) {
        int t  = tid >> 2;        // subtile 0..7
        int al = tid & 3;         // a_local 0..3
        float* r = sred + t * 16 + al * 4;
        float v = fmaxf(fmaxf(r[0], r[1]), fmaxf(r[2], r[3]));
        g_scores[(p * 4 + al) * NB + (s * 8 + t)] = v;
    }

    // ---- last-CTA fused final reduction ----
    __threadfence();
    __syncthreads();
    if (tid == 0) s_last = (atomicAdd(&g_done, 1u) == 127u);
    __syncthreads();
    if (!s_last) return;
    if (tid == 0) g_done = 0;     // reset for graph replay determinism

    // avg off-diag similarity: (||sum||^2 - S) / (S*(S-1)) (unit-norm tokens)
    for (int b = wid; b < NB; b += 8) {
        float4 vq = ((const float4*)g_sumq)[b * 32 + lane];
        float4 vd = ((const float4*)g_sumd)[b * 32 + lane];
        float sq = vq.x*vq.x + vq.y*vq.y + vq.z*vq.z + vq.w*vq.w;
        float sd = vd.x*vd.x + vd.y*vd.y + vd.z*vd.z + vd.w*vd.w;
        #pragma unroll
        for (int o = 16; o; o >>= 1) {
            sq += __shfl_xor_sync(0xffffffffu, sq, o);
            sd += __shfl_xor_sync(0xffffffffu, sd, o);
        }
        if (lane == 0) {
            s_avgq[b] = (sq - (float)SQ) * (1.0f / ((float)SQ * (SQ - 1)));
            s_avgd[b] = (sd - (float)SD) * (1.0f / ((float)SD * (SD - 1)));
        }
    }
    __syncthreads();

    // lse per row: warp wid handles rows wid*8 .. wid*8+7, 2 cols per lane
    #pragma unroll
    for (int r = 0; r < 8; r++) {
        int a = wid * 8 + r;
        float v0 = __ldcg(&g_scores[a * NB + lane]);
        float v1 = __ldcg(&g_scores[a * NB + 32 + lane]);
        float mx = fmaxf(v0, v1);
        #pragma unroll
        for (int o = 16; o; o >>= 1) mx = fmaxf(mx, __shfl_xor_sync(0xffffffffu, mx, o));
        float sum = expf(v0 - mx) + expf(v1 - mx);
        #pragma unroll
        for (int o = 16; o; o >>= 1) sum += __shfl_xor_sync(0xffffffffu, sum, o);
        if (lane == 0) {
            float diag = __ldcg(&g_scores[a * NB + a]);
            s_red[a] = mx + logf(sum) - diag + s_avgq[a] + s_avgd[a];
        }
    }
    __syncthreads();
    if (tid < 32) {
        float v = s_red[tid] + s_red[tid + 32];
        #pragma unroll
        for (int o = 16; o; o >>= 1) v += __shfl_xor_sync(0xffffffffu, v, o);
        if (tid == 0) out[0] = v * (1.0f / NB);
    }
}

// ---------------------------------------------------------------------------
extern "C" void kernel_launch(void* const* d_in, const int* in_sizes, int n_in,
                              void* d_out, int out_size)
{
    const float* q_emb  = (const float*)d_in[0];
    const float* d_emb  = (const float*)d_in[1];
    const int*   q_mask = (const int*)  d_in[2];
    const int*   d_mask = (const int*)  d_in[3];
    float*       out    = (float*)d_out;

    cudaFuncSetAttribute(maxgemm_kernel,
                         cudaFuncAttributeMaxDynamicSharedMemorySize, SMEM_BYTES);

    float *sumq, *sumd;
    cudaGetSymbolAddress((void**)&sumq, g_sumq);
    cudaGetSymbolAddress((void**)&sumd, g_sumd);

    cudaMemsetAsync(sumq, 0, NB * H * sizeof(float));
    cudaMemsetAsync(sumd, 0, NB * H * sizeof(float));
    normsplit_all<<<256 + 2048, 256>>>(q_emb, d_emb, q_mask, d_mask);
    maxgemm_kernel<<<dim3(16, 8), 256, SMEM_BYTES>>>(out);
}